// round 4
// baseline (speedup 1.0000x reference)
#include <cuda_runtime.h>
#include <cuda_bf16.h>
#include <math_constants.h>

#define BB 256
#define LL 512
#define HH 64
#define VV 64
#define NROWS (BB*LL)   // 131072

typedef unsigned long long u64;

__device__ __forceinline__ u64 pk2(float lo, float hi) {
    u64 r; asm("mov.b64 %0,{%1,%2};" : "=l"(r) : "f"(lo), "f"(hi)); return r;
}
__device__ __forceinline__ void upk2(u64 x, float& lo, float& hi) {
    asm("mov.b64 {%0,%1},%2;" : "=f"(lo), "=f"(hi) : "l"(x));
}
__device__ __forceinline__ u64 fma2(u64 a, u64 b, u64 c) {
    u64 d; asm("fma.rn.f32x2 %0,%1,%2,%3;" : "=l"(d) : "l"(a), "l"(b), "l"(c)); return d;
}

// ---- scratch (global __device__, no allocation) ----
__device__ float g_h [NROWS*HH];
__device__ float g_q [NROWS*HH];
__device__ float g_k [NROWS*HH];
__device__ float g_v [NROWS*HH];
__device__ float g_ao[NROWS*HH];
__device__ float g_h2[NROWS*HH];
__device__ float g_gs[NROWS];
__device__ float g_loss[BB];

// ============================================================
// K1: h = embed[seq];  qkv = h @ W_in^T + b_in
// warp per 2 rows (weight LDS amortized over the pair)
// ============================================================
#define K1_SMEM ((64*192 + 192 + 8*128)*4)
__global__ void __launch_bounds__(256) k1_embed_qkv(
    const float* __restrict__ embed,
    const float* __restrict__ W_in,
    const float* __restrict__ b_in,
    const int*   __restrict__ seq)
{
    extern __shared__ __align__(16) char smraw[];
    float* sm = (float*)smraw;
    float* WT = sm;                 // [d*192+o] = W_in[o*64+d]
    float* bb = WT + 64*192;        // 192
    float* hb = bb + 192;           // 8 warps * 128 (2 rows)
    int tid = threadIdx.x;
    for (int i = tid; i < 64*192; i += blockDim.x) {
        int d = i / 192, o = i % 192;
        WT[i] = W_in[o*64 + d];
    }
    for (int i = tid; i < 192; i += blockDim.x) bb[i] = b_in[i];
    __syncthreads();

    int warp = tid >> 5, lane = tid & 31;
    int gw = blockIdx.x * 8 + warp;
    int nw = gridDim.x * 8;
    float* hw = hb + warp*128;

    for (int pr = gw; pr < NROWS/2; pr += nw) {
        int r0 = pr*2, r1 = r0 + 1;
        int tok0 = seq[r0], tok1 = seq[r1];
        float e00 = embed[tok0*64 + lane], e01 = embed[tok0*64 + lane + 32];
        float e10 = embed[tok1*64 + lane], e11 = embed[tok1*64 + lane + 32];
        hw[lane] = e00; hw[lane+32] = e01;
        hw[64+lane] = e10; hw[96+lane] = e11;
        __syncwarp();
        float a0[6], a1[6];
        #pragma unroll
        for (int j = 0; j < 6; j++) { a0[j] = bb[lane + 32*j]; a1[j] = a0[j]; }
        #pragma unroll
        for (int d = 0; d < 64; d++) {
            float ha = hw[d], hc = hw[64+d];
            #pragma unroll
            for (int j = 0; j < 6; j++) {
                float w = WT[d*192 + lane + 32*j];
                a0[j] += ha * w;
                a1[j] += hc * w;
            }
        }
        g_h[r0*64+lane] = e00;  g_h[r0*64+lane+32] = e01;
        g_h[r1*64+lane] = e10;  g_h[r1*64+lane+32] = e11;
        g_q[r0*64+lane] = a0[0]; g_q[r0*64+lane+32] = a0[1];
        g_k[r0*64+lane] = a0[2]; g_k[r0*64+lane+32] = a0[3];
        g_v[r0*64+lane] = a0[4]; g_v[r0*64+lane+32] = a0[5];
        g_q[r1*64+lane] = a1[0]; g_q[r1*64+lane+32] = a1[1];
        g_k[r1*64+lane] = a1[2]; g_k[r1*64+lane+32] = a1[3];
        g_v[r1*64+lane] = a1[4]; g_v[r1*64+lane+32] = a1[5];
        __syncwarp();
    }
}

// ============================================================
// K2: attention, one CTA per (b, head).
//   f32x2 packed math; K tile pitch-18 u64 (LDS.128, conflict-free);
//   scores interleaved (row0,row1) -> one broadcast LDS.128 in AV.
//   Warp processes 2 q-rows per pass.
// ============================================================
#define K2_SMEM ((512*18 + 256*32 + 8*512)*8)
__global__ void __launch_bounds__(256,1) k2_attn()
{
    extern __shared__ __align__(16) char smraw[];
    u64* Ku = (u64*)smraw;          // [key*18 + dp], dp<16 used; 144B row, 16B aligned
    u64* Vu = Ku + 512*18;          // [p*32 + d] = (V[p][d], V[p+256][d])
    u64* SC = Vu + 256*32;          // per warp: 256 ulonglong2 (row0, row1 interleaved)

    int bh = blockIdx.x;
    int b = bh >> 1, hd = bh & 1;
    int tid = threadIdx.x;
    int base = (b*512)*64 + hd*32;

    for (int i = tid; i < 512*16; i += 256) {
        int key = i >> 4, dp = i & 15;
        Ku[key*18 + dp] = *(const u64*)&g_k[base + key*64 + 2*dp];
    }
    for (int i = tid; i < 256*32; i += 256) {
        int p = i >> 5, d = i & 31;
        Vu[p*32 + d] = pk2(g_v[base + p*64 + d], g_v[base + (p+256)*64 + d]);
    }
    __syncthreads();

    int warp = tid >> 5, lane = tid & 31;
    ulonglong2* scw = (ulonglong2*)(SC + warp*512);   // [p] = (row0 pack, row1 pack)
    const float scale = 0.17677669529663687f;   // 1/sqrt(32)

    for (int it = 0; it < 32; ++it) {
        int lq0 = it*16 + warp*2;
        int lq1 = lq0 + 1;

        u64 q0[16], q1[16];
        const u64* q0p = (const u64*)&g_q[base + lq0*64];
        const u64* q1p = (const u64*)&g_q[base + lq1*64];
        #pragma unroll
        for (int dp = 0; dp < 16; dp++) { q0[dp] = q0p[dp]; q1[dp] = q1p[dp]; }

        u64 a0[16], a1[16];
        #pragma unroll
        for (int kk = 0; kk < 16; kk++) { a0[kk] = 0ull; a1[kk] = 0ull; }

        // key owned by this lane for group kk: key = lane + kk*32
        #pragma unroll
        for (int kk = 0; kk < 16; kk++) {
            const ulonglong2* kr = (const ulonglong2*)(Ku + (lane + kk*32)*18);
            #pragma unroll
            for (int dq = 0; dq < 8; dq++) {
                ulonglong2 kv = kr[dq];
                a0[kk] = fma2(q0[2*dq],   kv.x, a0[kk]);
                a1[kk] = fma2(q1[2*dq],   kv.x, a1[kk]);
                a0[kk] = fma2(q0[2*dq+1], kv.y, a0[kk]);
                a1[kk] = fma2(q1[2*dq+1], kv.y, a1[kk]);
            }
        }

        // ---- softmax (both rows) ----
        float s0[16], s1[16];
        #pragma unroll
        for (int kk = 0; kk < 16; kk++) {
            float lo, hi;
            upk2(a0[kk], lo, hi); s0[kk] = (lo + hi) * scale;
            upk2(a1[kk], lo, hi); s1[kk] = (lo + hi) * scale;
        }
        float m0 = s0[0], m1 = s1[0];
        #pragma unroll
        for (int kk = 1; kk < 16; kk++) { m0 = fmaxf(m0, s0[kk]); m1 = fmaxf(m1, s1[kk]); }
        #pragma unroll
        for (int o = 16; o; o >>= 1) {
            m0 = fmaxf(m0, __shfl_xor_sync(0xffffffffu, m0, o));
            m1 = fmaxf(m1, __shfl_xor_sync(0xffffffffu, m1, o));
        }
        // pair kk (key p = lane+32*kk < 256) with kk+8 (key p+256):
        // one STS.128 per pair holding both rows, conflict-free, AV layout.
        float sum0 = 0.f, sum1 = 0.f;
        #pragma unroll
        for (int kk = 0; kk < 8; kk++) {
            int p = lane + 32*kk;
            float e0lo = __expf(s0[kk]   - m0);
            float e0hi = __expf(s0[kk+8] - m0);
            float e1lo = __expf(s1[kk]   - m1);
            float e1hi = __expf(s1[kk+8] - m1);
            sum0 += e0lo + e0hi;
            sum1 += e1lo + e1hi;
            ulonglong2 sv;
            sv.x = pk2(e0lo, e0hi);
            sv.y = pk2(e1lo, e1hi);
            scw[p] = sv;
        }
        #pragma unroll
        for (int o = 16; o; o >>= 1) {
            sum0 += __shfl_xor_sync(0xffffffffu, sum0, o);
            sum1 += __shfl_xor_sync(0xffffffffu, sum1, o);
        }
        float inv0 = 1.f / sum0, inv1 = 1.f / sum1;
        __syncwarp();

        // ---- AV, key-pair packed; one broadcast LDS.128 per p ----
        u64 ac0 = 0ull, ac1 = 0ull;
        #pragma unroll 4
        for (int p = 0; p < 256; p++) {
            ulonglong2 sv = scw[p];
            u64 v2 = Vu[p*32 + lane];
            ac0 = fma2(sv.x, v2, ac0);
            ac1 = fma2(sv.y, v2, ac1);
        }
        {
            float lo, hi;
            upk2(ac0, lo, hi);
            g_ao[base + lq0*64 + lane] = (lo + hi) * inv0;
            upk2(ac1, lo, hi);
            g_ao[base + lq1*64 + lane] = (lo + hi) * inv1;
        }
        __syncwarp();
    }
}

// ============================================================
// K3: W_out + resid + LN1 + FFN + LN2 + lm loss_per_token + gate
// warp per 2 rows (weight LDS amortized); weights transposed in smem
// ============================================================
#define K3_SMEM ((4096 + 8192 + 8192 + 4096 + 644 + 8*384)*4)
__global__ void __launch_bounds__(256,2) k3_fused(
        const float* __restrict__ W_out, const float* __restrict__ b_out,
        const float* __restrict__ ln1g,  const float* __restrict__ ln1b,
        const float* __restrict__ W1,    const float* __restrict__ b1,
        const float* __restrict__ W2,    const float* __restrict__ b2,
        const float* __restrict__ ln2g,  const float* __restrict__ ln2b,
        const float* __restrict__ lmW,   const float* __restrict__ lmb,
        const float* __restrict__ gateW, const float* __restrict__ gateb,
        const int*   __restrict__ seq,   float* __restrict__ out)
{
    extern __shared__ __align__(16) char smraw[];
    float* sm = (float*)smraw;
    float* WoT = sm;            // [d*64+o]
    float* W1T = WoT + 4096;    // [d*128+o], o<128
    float* W2T = W1T + 8192;    // [d*64+o],  d<128
    float* LmT = W2T + 8192;    // [d*64+o]
    float* cb  = LmT + 4096;    // 644
    float* WS  = cb + 644;      // 8 warps * 384

    int tid = threadIdx.x;
    for (int i = tid; i < 4096; i += blockDim.x) {
        int o = i >> 6, d = i & 63;
        WoT[d*64 + o] = W_out[i];
        LmT[d*64 + o] = lmW[i];
    }
    for (int i = tid; i < 8192; i += blockDim.x) {
        { int o = i >> 6, d = i & 63;  W1T[d*128 + o] = W1[i]; }
        { int o = i >> 7, d = i & 127; W2T[d*64  + o] = W2[i]; }
    }
    for (int i = tid; i < 64; i += blockDim.x) {
        cb[i]     = b_out[i];
        cb[64+i]  = ln1g[i];
        cb[128+i] = ln1b[i];
        cb[320+i] = b2[i];
        cb[384+i] = ln2g[i];
        cb[448+i] = ln2b[i];
        cb[512+i] = lmb[i];
        cb[576+i] = gateW[i];
    }
    for (int i = tid; i < 128; i += blockDim.x) cb[192+i] = b1[i];
    if (tid == 0) cb[640] = gateb[0];
    __syncthreads();

    int warp = tid >> 5, lane = tid & 31;
    float* M0 = WS + warp*384;   // 64: ao / h1 / h2 for row0
    float* M1 = M0 + 64;
    float* U0 = M0 + 128;        // 128
    float* U1 = M0 + 256;        // 128
    int gw = blockIdx.x*8 + warp, nw = gridDim.x*8;
    const float inv64 = 1.f/64.f;
    int t = lane;

    for (int pr = gw; pr < NROWS/2; pr += nw) {
        int r0 = pr*2, r1 = r0 + 1;
        float h00 = g_h[r0*64+t], h01 = g_h[r0*64+t+32];
        float h10 = g_h[r1*64+t], h11 = g_h[r1*64+t+32];
        M0[t] = g_ao[r0*64+t]; M0[t+32] = g_ao[r0*64+t+32];
        M1[t] = g_ao[r1*64+t]; M1[t+32] = g_ao[r1*64+t+32];
        __syncwarp();

        // W_out GEMV (both rows share weight loads)
        float a00 = cb[t], a01 = cb[t+32];
        float a10 = a00,   a11 = a01;
        #pragma unroll
        for (int d = 0; d < 64; d++) {
            float w0 = WoT[d*64 + t], w1 = WoT[d*64 + t + 32];
            float v0 = M0[d], v1 = M1[d];
            a00 += v0*w0; a01 += v0*w1;
            a10 += v1*w0; a11 += v1*w1;
        }
        float x00 = h00+a00, x01 = h01+a01, x10 = h10+a10, x11 = h11+a11;

        // LN1 (per row)
        float s0 = x00+x01, s1 = x10+x11;
        #pragma unroll
        for (int o = 16; o; o >>= 1) {
            s0 += __shfl_xor_sync(0xffffffffu, s0, o);
            s1 += __shfl_xor_sync(0xffffffffu, s1, o);
        }
        float mn0 = s0*inv64, mn1 = s1*inv64;
        float d00 = x00-mn0, d01 = x01-mn0, d10 = x10-mn1, d11 = x11-mn1;
        float v0 = d00*d00 + d01*d01, v1 = d10*d10 + d11*d11;
        #pragma unroll
        for (int o = 16; o; o >>= 1) {
            v0 += __shfl_xor_sync(0xffffffffu, v0, o);
            v1 += __shfl_xor_sync(0xffffffffu, v1, o);
        }
        float rs0 = rsqrtf(v0*inv64 + 1e-5f), rs1 = rsqrtf(v1*inv64 + 1e-5f);
        float y00 = d00*rs0*cb[64+t]    + cb[128+t];
        float y01 = d01*rs0*cb[64+t+32] + cb[128+t+32];
        float y10 = d10*rs1*cb[64+t]    + cb[128+t];
        float y11 = d11*rs1*cb[64+t+32] + cb[128+t+32];
        __syncwarp();
        M0[t] = y00; M0[t+32] = y01;
        M1[t] = y10; M1[t+32] = y11;
        __syncwarp();

        // FFN up + relu
        float u0[4], u1[4];
        #pragma unroll
        for (int j = 0; j < 4; j++) { u0[j] = cb[192 + t + 32*j]; u1[j] = u0[j]; }
        #pragma unroll
        for (int d = 0; d < 64; d++) {
            float hv0 = M0[d], hv1 = M1[d];
            #pragma unroll
            for (int j = 0; j < 4; j++) {
                float w = W1T[d*128 + t + 32*j];
                u0[j] += hv0*w;
                u1[j] += hv1*w;
            }
        }
        #pragma unroll
        for (int j = 0; j < 4; j++) {
            U0[t + 32*j] = fmaxf(u0[j], 0.f);
            U1[t + 32*j] = fmaxf(u1[j], 0.f);
        }
        __syncwarp();

        // FFN down
        float f00 = cb[320+t], f01 = cb[320+t+32];
        float f10 = f00,       f11 = f01;
        #pragma unroll
        for (int d = 0; d < 128; d++) {
            float w0 = W2T[d*64 + t], w1 = W2T[d*64 + t + 32];
            float uv0 = U0[d], uv1 = U1[d];
            f00 += uv0*w0; f01 += uv0*w1;
            f10 += uv1*w0; f11 += uv1*w1;
        }
        float z00 = y00+f00, z01 = y01+f01, z10 = y10+f10, z11 = y11+f11;

        // LN2
        s0 = z00+z01; s1 = z10+z11;
        #pragma unroll
        for (int o = 16; o; o >>= 1) {
            s0 += __shfl_xor_sync(0xffffffffu, s0, o);
            s1 += __shfl_xor_sync(0xffffffffu, s1, o);
        }
        mn0 = s0*inv64; mn1 = s1*inv64;
        d00 = z00-mn0; d01 = z01-mn0; d10 = z10-mn1; d11 = z11-mn1;
        v0 = d00*d00 + d01*d01; v1 = d10*d10 + d11*d11;
        #pragma unroll
        for (int o = 16; o; o >>= 1) {
            v0 += __shfl_xor_sync(0xffffffffu, v0, o);
            v1 += __shfl_xor_sync(0xffffffffu, v1, o);
        }
        rs0 = rsqrtf(v0*inv64 + 1e-5f); rs1 = rsqrtf(v1*inv64 + 1e-5f);
        float q00 = d00*rs0*cb[384+t]    + cb[448+t];
        float q01 = d01*rs0*cb[384+t+32] + cb[448+t+32];
        float q10 = d10*rs1*cb[384+t]    + cb[448+t];
        float q11 = d11*rs1*cb[384+t+32] + cb[448+t+32];
        __syncwarp();
        M0[t] = q00; M0[t+32] = q01;
        M1[t] = q10; M1[t+32] = q11;
        g_h2[r0*64+t] = q00; g_h2[r0*64+t+32] = q01;
        g_h2[r1*64+t] = q10; g_h2[r1*64+t+32] = q11;
        __syncwarp();

        // lm head
        float l00 = cb[512+t], l01 = cb[512+t+32];
        float l10 = l00,       l11 = l01;
        #pragma unroll
        for (int d = 0; d < 64; d++) {
            float w0 = LmT[d*64 + t], w1 = LmT[d*64 + t + 32];
            float hv0 = M0[d], hv1 = M1[d];
            l00 += hv0*w0; l01 += hv0*w1;
            l10 += hv1*w0; l11 += hv1*w1;
        }
        // log-sum-exp per row
        float m0 = fmaxf(l00, l01), m1 = fmaxf(l10, l11);
        #pragma unroll
        for (int o = 16; o; o >>= 1) {
            m0 = fmaxf(m0, __shfl_xor_sync(0xffffffffu, m0, o));
            m1 = fmaxf(m1, __shfl_xor_sync(0xffffffffu, m1, o));
        }
        float es0 = __expf(l00-m0) + __expf(l01-m0);
        float es1 = __expf(l10-m1) + __expf(l11-m1);
        #pragma unroll
        for (int o = 16; o; o >>= 1) {
            es0 += __shfl_xor_sync(0xffffffffu, es0, o);
            es1 += __shfl_xor_sync(0xffffffffu, es1, o);
        }
        float lse0 = m0 + logf(es0);
        float lse1 = m1 + logf(es1);

        // target logits via shuffle (no shared LG buffer)
        int l0pos = r0 & 511, l1pos = r1 & 511;
        int tgt0 = (l0pos == 511) ? 0 : seq[r0+1];
        int tgt1 = (l1pos == 511) ? 0 : seq[r1+1];
        float cand0 = (tgt0 < 32) ? l00 : l01;
        float cand1 = (tgt1 < 32) ? l10 : l11;
        float tl0 = __shfl_sync(0xffffffffu, cand0, tgt0 & 31);
        float tl1 = __shfl_sync(0xffffffffu, cand1, tgt1 & 31);

        // gate score
        float gv0 = q00*cb[576+t] + q01*cb[576+t+32];
        float gv1 = q10*cb[576+t] + q11*cb[576+t+32];
        #pragma unroll
        for (int o = 16; o; o >>= 1) {
            gv0 += __shfl_xor_sync(0xffffffffu, gv0, o);
            gv1 += __shfl_xor_sync(0xffffffffu, gv1, o);
        }
        __syncwarp();

        if (lane == 0) {
            g_gs[r0] = gv0 + cb[640];
            g_gs[r1] = gv1 + cb[640];
            out[1 + r0] = (l0pos == 511) ? 0.f : (lse0 - tl0);
            out[1 + r1] = (l1pos == 511) ? 0.f : (lse1 - tl1);
        }
        __syncwarp();
    }
}

// ============================================================
// K4: per-batch top-8 + memory reader + per-batch loss
// ============================================================
__global__ void k4_reader(const float* __restrict__ qembed,
                          const float* __restrict__ qpW, const float* __restrict__ qpb,
                          const float* __restrict__ opW, const float* __restrict__ opb,
                          const int* __restrict__ query, const int* __restrict__ target)
{
    __shared__ float gs[512];
    __shared__ int   chosen[8];
    __shared__ float keys[8*64];
    __shared__ float qh[64], qp[64], rs[8], rw[8], ret[64], lg[64];
    __shared__ float red[256]; __shared__ int redi[256];

    int b = blockIdx.x, tid = threadIdx.x;
    gs[tid]     = g_gs[b*512 + tid];
    gs[tid+256] = g_gs[b*512 + tid + 256];
    __syncthreads();

    // stable top-8 (higher value first; ties -> lower index)
    for (int k = 0; k < 8; k++) {
        float best = -CUDART_INF_F; int bi = 0x7fffffff;
        for (int l = tid; l < 512; l += 256) {
            bool taken = false;
            for (int j = 0; j < k; j++) if (chosen[j] == l) taken = true;
            if (!taken) {
                float vv = gs[l];
                if (vv > best || (vv == best && l < bi)) { best = vv; bi = l; }
            }
        }
        red[tid] = best; redi[tid] = bi;
        __syncthreads();
        for (int s = 128; s; s >>= 1) {
            if (tid < s) {
                if (red[tid+s] > red[tid] ||
                    (red[tid+s] == red[tid] && redi[tid+s] < redi[tid])) {
                    red[tid] = red[tid+s]; redi[tid] = redi[tid+s];
                }
            }
            __syncthreads();
        }
        if (tid == 0) chosen[k] = redi[0];
        __syncthreads();
    }

    for (int i = tid; i < 512; i += 256) {
        int k = i >> 6, d = i & 63;
        keys[i] = g_h2[(b*512 + chosen[k])*64 + d];
    }
    if (tid < 64) qh[tid] = qembed[query[b]*64 + tid];
    __syncthreads();

    if (tid < 64) {
        float a = qpb[tid];
        for (int d = 0; d < 64; d++) a += qpW[tid*64 + d] * qh[d];
        qp[tid] = a;
    }
    __syncthreads();
    if (tid < 8) {
        float a = 0.f;
        for (int d = 0; d < 64; d++) a += qp[d] * keys[tid*64 + d];
        rs[tid] = a * 0.125f;   // 1/sqrt(64)
    }
    __syncthreads();
    if (tid == 0) {
        float m = rs[0];
        for (int k = 1; k < 8; k++) m = fmaxf(m, rs[k]);
        float s = 0.f;
        for (int k = 0; k < 8; k++) { rw[k] = __expf(rs[k] - m); s += rw[k]; }
        float inv = 1.f / s;
        for (int k = 0; k < 8; k++) rw[k] *= inv;
    }
    __syncthreads();
    if (tid < 64) {
        float a = 0.f;
        for (int k = 0; k < 8; k++) a += rw[k] * keys[k*64 + tid];
        ret[tid] = a;
    }
    __syncthreads();
    if (tid < 64) {
        float a = opb[tid];
        for (int d = 0; d < 64; d++) a += opW[tid*64 + d] * ret[d];
        lg[tid] = a;
    }
    __syncthreads();
    if (tid == 0) {
        float m = lg[0];
        for (int v = 1; v < 64; v++) m = fmaxf(m, lg[v]);
        float s = 0.f;
        for (int v = 0; v < 64; v++) s += __expf(lg[v] - m);
        float lse = m + logf(s);
        g_loss[b] = lse - lg[target[b]];
    }
}

// ============================================================
// K5: mean task loss -> out[0]
// ============================================================
__global__ void k5_final(float* __restrict__ out)
{
    __shared__ float red[256];
    int tid = threadIdx.x;
    red[tid] = g_loss[tid];
    __syncthreads();
    for (int s = 128; s; s >>= 1) {
        if (tid < s) red[tid] += red[tid+s];
        __syncthreads();
    }
    if (tid == 0) out[0] = red[0] * (1.f/256.f);
}

// ============================================================
extern "C" void kernel_launch(void* const* d_in, const int* in_sizes, int n_in,
                              void* d_out, int out_size)
{
    const float* embed  = (const float*)d_in[0];
    const float* qembed = (const float*)d_in[1];
    const float* W_in   = (const float*)d_in[2];
    const float* b_in   = (const float*)d_in[3];
    const float* W_out  = (const float*)d_in[4];
    const float* b_out  = (const float*)d_in[5];
    const float* ln1g   = (const float*)d_in[6];
    const float* ln1b   = (const float*)d_in[7];
    const float* W1     = (const float*)d_in[8];
    const float* b1     = (const float*)d_in[9];
    const float* W2     = (const float*)d_in[10];
    const float* b2     = (const float*)d_in[11];
    const float* ln2g   = (const float*)d_in[12];
    const float* ln2b   = (const float*)d_in[13];
    const float* lmW    = (const float*)d_in[14];
    const float* lmb    = (const float*)d_in[15];
    const float* gateW  = (const float*)d_in[16];
    const float* gateb  = (const float*)d_in[17];
    const float* qpW    = (const float*)d_in[18];
    const float* qpb    = (const float*)d_in[19];
    const float* opW    = (const float*)d_in[20];
    const float* opb    = (const float*)d_in[21];
    const int*   seq    = (const int*)d_in[22];
    const int*   query  = (const int*)d_in[23];
    const int*   target = (const int*)d_in[24];
    float* out = (float*)d_out;

    cudaFuncSetAttribute(k1_embed_qkv, cudaFuncAttributeMaxDynamicSharedMemorySize, K1_SMEM);
    cudaFuncSetAttribute(k2_attn,      cudaFuncAttributeMaxDynamicSharedMemorySize, K2_SMEM);
    cudaFuncSetAttribute(k3_fused,     cudaFuncAttributeMaxDynamicSharedMemorySize, K3_SMEM);

    k1_embed_qkv<<<512, 256, K1_SMEM>>>(embed, W_in, b_in, seq);
    k2_attn<<<512, 256, K2_SMEM>>>();
    k3_fused<<<1024, 256, K3_SMEM>>>(W_out, b_out, ln1g, ln1b, W1, b1, W2, b2,
                                     ln2g, ln2b, lmW, lmb, gateW, gateb, seq, out);
    k4_reader<<<256, 256>>>(qembed, qpW, qpb, opW, opb, query, target);
    k5_final<<<1, 256>>>(out);
}

// round 8
// speedup vs baseline: 1.0338x; 1.0338x over previous
#include <cuda_runtime.h>
#include <cuda_bf16.h>
#include <math_constants.h>

#define BB 256
#define LL 512
#define HH 64
#define VV 64
#define NROWS (BB*LL)   // 131072

typedef unsigned long long u64;

__device__ __forceinline__ u64 pk2(float lo, float hi) {
    u64 r; asm("mov.b64 %0,{%1,%2};" : "=l"(r) : "f"(lo), "f"(hi)); return r;
}
__device__ __forceinline__ void upk2(u64 x, float& lo, float& hi) {
    asm("mov.b64 {%0,%1},%2;" : "=f"(lo), "=f"(hi) : "l"(x));
}
__device__ __forceinline__ u64 fma2(u64 a, u64 b, u64 c) {
    u64 d; asm("fma.rn.f32x2 %0,%1,%2,%3;" : "=l"(d) : "l"(a), "l"(b), "l"(c)); return d;
}
__device__ __forceinline__ u64 add2(u64 a, u64 b) {
    u64 d; asm("add.rn.f32x2 %0,%1,%2;" : "=l"(d) : "l"(a), "l"(b)); return d;
}
__device__ __forceinline__ float hsum2(u64 a) {
    float lo, hi; upk2(a, lo, hi); return lo + hi;
}

// ---- scratch (global __device__, no allocation) ----
__device__ float g_h [NROWS*HH];
__device__ float g_q [NROWS*HH];
__device__ float g_k [NROWS*HH];
__device__ float g_v [NROWS*HH];
__device__ float g_ao[NROWS*HH];
__device__ float g_h2[NROWS*HH];
__device__ float g_gs[NROWS];
__device__ float g_loss[BB];

// ============================================================
// K1: h = embed[seq];  qkv = h @ W_in^T + b_in
// warp per 2 rows; weights as d-pair u64 (pitch 33), f32x2 math
// ============================================================
#define K1_SMEM (192*33*8 + 192*4 + 8*128*4)
__global__ void __launch_bounds__(256) k1_embed_qkv(
    const float* __restrict__ embed,
    const float* __restrict__ W_in,
    const float* __restrict__ b_in,
    const int*   __restrict__ seq)
{
    extern __shared__ __align__(16) char smraw[];
    u64*   Wiu = (u64*)smraw;              // [o*33+dp] = (W_in[o][2dp], W_in[o][2dp+1])
    float* bb  = (float*)(Wiu + 192*33);   // 192
    float* hb  = bb + 192;                 // 8 warps * 128 (2 rows)
    int tid = threadIdx.x;
    const u64* Wg = (const u64*)W_in;
    for (int i = tid; i < 192*32; i += 256) {
        int o = i >> 5, dp = i & 31;
        Wiu[o*33 + dp] = Wg[i];
    }
    for (int i = tid; i < 192; i += 256) bb[i] = b_in[i];
    __syncthreads();

    int warp = tid >> 5, lane = tid & 31;
    int gw = blockIdx.x * 8 + warp;
    int nw = gridDim.x * 8;
    float* hw = hb + warp*128;

    for (int pr = gw; pr < NROWS/2; pr += nw) {
        int r0 = pr*2, r1 = r0 + 1;
        int tok0 = seq[r0], tok1 = seq[r1];
        float e00 = embed[tok0*64 + lane], e01 = embed[tok0*64 + lane + 32];
        float e10 = embed[tok1*64 + lane], e11 = embed[tok1*64 + lane + 32];
        hw[lane] = e00; hw[lane+32] = e01;
        hw[64+lane] = e10; hw[96+lane] = e11;
        __syncwarp();

        u64 a0[6], a1[6];
        #pragma unroll
        for (int j = 0; j < 6; j++) { a0[j] = 0ull; a1[j] = 0ull; }
        #pragma unroll
        for (int dp = 0; dp < 32; dp++) {
            u64 h0v = *(const u64*)&hw[2*dp];
            u64 h1v = *(const u64*)&hw[64 + 2*dp];
            #pragma unroll
            for (int j = 0; j < 6; j++) {
                u64 w = Wiu[(lane + 32*j)*33 + dp];
                a0[j] = fma2(h0v, w, a0[j]);
                a1[j] = fma2(h1v, w, a1[j]);
            }
        }
        float o0[6], o1[6];
        #pragma unroll
        for (int j = 0; j < 6; j++) {
            o0[j] = hsum2(a0[j]) + bb[lane + 32*j];
            o1[j] = hsum2(a1[j]) + bb[lane + 32*j];
        }
        g_h[r0*64+lane] = e00;  g_h[r0*64+lane+32] = e01;
        g_h[r1*64+lane] = e10;  g_h[r1*64+lane+32] = e11;
        g_q[r0*64+lane] = o0[0]; g_q[r0*64+lane+32] = o0[1];
        g_k[r0*64+lane] = o0[2]; g_k[r0*64+lane+32] = o0[3];
        g_v[r0*64+lane] = o0[4]; g_v[r0*64+lane+32] = o0[5];
        g_q[r1*64+lane] = o1[0]; g_q[r1*64+lane+32] = o1[1];
        g_k[r1*64+lane] = o1[2]; g_k[r1*64+lane+32] = o1[3];
        g_v[r1*64+lane] = o1[4]; g_v[r1*64+lane+32] = o1[5];
        __syncwarp();
    }
}

// ============================================================
// K2: attention, one CTA per (b, head).
//   f32x2 packed; K tile pitch-18 u64 (LDS.128);
//   scores interleaved (row0,row1); AV with 4 accumulator chains/row.
// ============================================================
#define K2_SMEM ((512*18 + 256*32 + 8*512)*8)
__global__ void __launch_bounds__(256,1) k2_attn()
{
    extern __shared__ __align__(16) char smraw[];
    u64* Ku = (u64*)smraw;          // [key*18 + dp], dp<16 used
    u64* Vu = Ku + 512*18;          // [p*32 + d] = (V[p][d], V[p+256][d])
    u64* SC = Vu + 256*32;          // per warp: 256 ulonglong2

    int bh = blockIdx.x;
    int b = bh >> 1, hd = bh & 1;
    int tid = threadIdx.x;
    int base = (b*512)*64 + hd*32;

    for (int i = tid; i < 512*16; i += 256) {
        int key = i >> 4, dp = i & 15;
        Ku[key*18 + dp] = *(const u64*)&g_k[base + key*64 + 2*dp];
    }
    for (int i = tid; i < 256*32; i += 256) {
        int p = i >> 5, d = i & 31;
        Vu[p*32 + d] = pk2(g_v[base + p*64 + d], g_v[base + (p+256)*64 + d]);
    }
    __syncthreads();

    int warp = tid >> 5, lane = tid & 31;
    ulonglong2* scw = (ulonglong2*)(SC + warp*512);
    const float scale = 0.17677669529663687f;   // 1/sqrt(32)

    for (int it = 0; it < 32; ++it) {
        int lq0 = it*16 + warp*2;
        int lq1 = lq0 + 1;

        u64 q0[16], q1[16];
        const u64* q0p = (const u64*)&g_q[base + lq0*64];
        const u64* q1p = (const u64*)&g_q[base + lq1*64];
        #pragma unroll
        for (int dp = 0; dp < 16; dp++) { q0[dp] = q0p[dp]; q1[dp] = q1p[dp]; }

        u64 a0[16], a1[16];
        #pragma unroll
        for (int kk = 0; kk < 16; kk++) { a0[kk] = 0ull; a1[kk] = 0ull; }

        #pragma unroll
        for (int kk = 0; kk < 16; kk++) {
            const ulonglong2* kr = (const ulonglong2*)(Ku + (lane + kk*32)*18);
            #pragma unroll
            for (int dq = 0; dq < 8; dq++) {
                ulonglong2 kv = kr[dq];
                a0[kk] = fma2(q0[2*dq],   kv.x, a0[kk]);
                a1[kk] = fma2(q1[2*dq],   kv.x, a1[kk]);
                a0[kk] = fma2(q0[2*dq+1], kv.y, a0[kk]);
                a1[kk] = fma2(q1[2*dq+1], kv.y, a1[kk]);
            }
        }

        float s0[16], s1[16];
        #pragma unroll
        for (int kk = 0; kk < 16; kk++) {
            s0[kk] = hsum2(a0[kk]) * scale;
            s1[kk] = hsum2(a1[kk]) * scale;
        }
        float m0 = s0[0], m1 = s1[0];
        #pragma unroll
        for (int kk = 1; kk < 16; kk++) { m0 = fmaxf(m0, s0[kk]); m1 = fmaxf(m1, s1[kk]); }
        #pragma unroll
        for (int o = 16; o; o >>= 1) {
            m0 = fmaxf(m0, __shfl_xor_sync(0xffffffffu, m0, o));
            m1 = fmaxf(m1, __shfl_xor_sync(0xffffffffu, m1, o));
        }
        float sum0 = 0.f, sum1 = 0.f;
        #pragma unroll
        for (int kk = 0; kk < 8; kk++) {
            int p = lane + 32*kk;
            float e0lo = __expf(s0[kk]   - m0);
            float e0hi = __expf(s0[kk+8] - m0);
            float e1lo = __expf(s1[kk]   - m1);
            float e1hi = __expf(s1[kk+8] - m1);
            sum0 += e0lo + e0hi;
            sum1 += e1lo + e1hi;
            ulonglong2 sv;
            sv.x = pk2(e0lo, e0hi);
            sv.y = pk2(e1lo, e1hi);
            scw[p] = sv;
        }
        #pragma unroll
        for (int o = 16; o; o >>= 1) {
            sum0 += __shfl_xor_sync(0xffffffffu, sum0, o);
            sum1 += __shfl_xor_sync(0xffffffffu, sum1, o);
        }
        float inv0 = 1.f / sum0, inv1 = 1.f / sum1;
        __syncwarp();

        // ---- AV: 4 independent chains per row (hide FFMA latency) ----
        u64 ac0[4], ac1[4];
        #pragma unroll
        for (int c = 0; c < 4; c++) { ac0[c] = 0ull; ac1[c] = 0ull; }
        #pragma unroll 2
        for (int p = 0; p < 64; p++) {
            #pragma unroll
            for (int c = 0; c < 4; c++) {
                int pp = p + 64*c;
                ulonglong2 sv = scw[pp];
                u64 v2 = Vu[pp*32 + lane];
                ac0[c] = fma2(sv.x, v2, ac0[c]);
                ac1[c] = fma2(sv.y, v2, ac1[c]);
            }
        }
        u64 t0 = add2(add2(ac0[0], ac0[1]), add2(ac0[2], ac0[3]));
        u64 t1 = add2(add2(ac1[0], ac1[1]), add2(ac1[2], ac1[3]));
        g_ao[base + lq0*64 + lane] = hsum2(t0) * inv0;
        g_ao[base + lq1*64 + lane] = hsum2(t1) * inv1;
        __syncwarp();
    }
}

// ============================================================
// K3: W_out + resid + LN1 + FFN + LN2 + lm loss_per_token + gate
// warp per 2 rows; weights as d-pair u64 rows, f32x2 GEMVs
// ============================================================
#define K3_SMEM ((2112+4224+4160+2112)*8 + 644*4 + 8*384*4)
__global__ void __launch_bounds__(256,2) k3_fused(
        const float* __restrict__ W_out, const float* __restrict__ b_out,
        const float* __restrict__ ln1g,  const float* __restrict__ ln1b,
        const float* __restrict__ W1,    const float* __restrict__ b1,
        const float* __restrict__ W2,    const float* __restrict__ b2,
        const float* __restrict__ ln2g,  const float* __restrict__ ln2b,
        const float* __restrict__ lmW,   const float* __restrict__ lmb,
        const float* __restrict__ gateW, const float* __restrict__ gateb,
        const int*   __restrict__ seq,   float* __restrict__ out)
{
    extern __shared__ __align__(16) char smraw[];
    u64*   Wou = (u64*)smraw;          // [o*33+dp], o<64, dp<32
    u64*   W1u = Wou + 2112;           // [o*33+dp], o<128
    u64*   W2u = W1u + 4224;           // [o*65+dp], o<64, dp<64
    u64*   Lmu = W2u + 4160;           // [o*33+dp], o<64
    float* cb  = (float*)(Lmu + 2112); // 644
    float* WS  = cb + 644;             // 8 warps * 384

    int tid = threadIdx.x;
    const u64* Wog = (const u64*)W_out;
    const u64* Lmg = (const u64*)lmW;
    const u64* W1g = (const u64*)W1;
    const u64* W2g = (const u64*)W2;
    for (int i = tid; i < 64*32; i += 256) {
        int o = i >> 5, dp = i & 31;
        Wou[o*33 + dp] = Wog[i];
        Lmu[o*33 + dp] = Lmg[i];
    }
    for (int i = tid; i < 128*32; i += 256) {
        int o = i >> 5, dp = i & 31;
        W1u[o*33 + dp] = W1g[i];
    }
    for (int i = tid; i < 64*64; i += 256) {
        int o = i >> 6, dp = i & 63;
        W2u[o*65 + dp] = W2g[i];
    }
    for (int i = tid; i < 64; i += 256) {
        cb[i]     = b_out[i];
        cb[64+i]  = ln1g[i];
        cb[128+i] = ln1b[i];
        cb[320+i] = b2[i];
        cb[384+i] = ln2g[i];
        cb[448+i] = ln2b[i];
        cb[512+i] = lmb[i];
        cb[576+i] = gateW[i];
    }
    for (int i = tid; i < 128; i += 256) cb[192+i] = b1[i];
    if (tid == 0) cb[640] = gateb[0];
    __syncthreads();

    int warp = tid >> 5, lane = tid & 31;
    float* M0 = WS + warp*384;
    float* M1 = M0 + 64;
    float* U0 = M0 + 128;        // 128
    float* U1 = M0 + 256;        // 128
    int gw = blockIdx.x*8 + warp, nw = gridDim.x*8;
    const float inv64 = 1.f/64.f;
    int t = lane;

    for (int pr = gw; pr < NROWS/2; pr += nw) {
        int r0 = pr*2, r1 = r0 + 1;
        float h00 = g_h[r0*64+t], h01 = g_h[r0*64+t+32];
        float h10 = g_h[r1*64+t], h11 = g_h[r1*64+t+32];
        M0[t] = g_ao[r0*64+t]; M0[t+32] = g_ao[r0*64+t+32];
        M1[t] = g_ao[r1*64+t]; M1[t+32] = g_ao[r1*64+t+32];
        __syncwarp();

        // ---- W_out GEMV (f32x2 over d-pairs) ----
        u64 a0p0 = 0ull, a0p1 = 0ull, a1p0 = 0ull, a1p1 = 0ull;
        #pragma unroll
        for (int dp = 0; dp < 32; dp++) {
            u64 mv0 = *(const u64*)&M0[2*dp];
            u64 mv1 = *(const u64*)&M1[2*dp];
            u64 w0 = Wou[t*33 + dp];
            u64 w1 = Wou[(t+32)*33 + dp];
            a0p0 = fma2(mv0, w0, a0p0);
            a0p1 = fma2(mv0, w1, a0p1);
            a1p0 = fma2(mv1, w0, a1p0);
            a1p1 = fma2(mv1, w1, a1p1);
        }
        float x00 = h00 + hsum2(a0p0) + cb[t];
        float x01 = h01 + hsum2(a0p1) + cb[t+32];
        float x10 = h10 + hsum2(a1p0) + cb[t];
        float x11 = h11 + hsum2(a1p1) + cb[t+32];

        // ---- LN1 ----
        float s0 = x00+x01, s1 = x10+x11;
        #pragma unroll
        for (int o = 16; o; o >>= 1) {
            s0 += __shfl_xor_sync(0xffffffffu, s0, o);
            s1 += __shfl_xor_sync(0xffffffffu, s1, o);
        }
        float mn0 = s0*inv64, mn1 = s1*inv64;
        float d00 = x00-mn0, d01 = x01-mn0, d10 = x10-mn1, d11 = x11-mn1;
        float v0 = d00*d00 + d01*d01, v1 = d10*d10 + d11*d11;
        #pragma unroll
        for (int o = 16; o; o >>= 1) {
            v0 += __shfl_xor_sync(0xffffffffu, v0, o);
            v1 += __shfl_xor_sync(0xffffffffu, v1, o);
        }
        float rs0 = rsqrtf(v0*inv64 + 1e-5f), rs1 = rsqrtf(v1*inv64 + 1e-5f);
        float y00 = d00*rs0*cb[64+t]    + cb[128+t];
        float y01 = d01*rs0*cb[64+t+32] + cb[128+t+32];
        float y10 = d10*rs1*cb[64+t]    + cb[128+t];
        float y11 = d11*rs1*cb[64+t+32] + cb[128+t+32];
        __syncwarp();
        M0[t] = y00; M0[t+32] = y01;
        M1[t] = y10; M1[t+32] = y11;
        __syncwarp();

        // ---- FFN up + relu (128 outputs, 4 per lane) ----
        u64 u0p[4], u1p[4];
        #pragma unroll
        for (int j = 0; j < 4; j++) { u0p[j] = 0ull; u1p[j] = 0ull; }
        #pragma unroll
        for (int dp = 0; dp < 32; dp++) {
            u64 mv0 = *(const u64*)&M0[2*dp];
            u64 mv1 = *(const u64*)&M1[2*dp];
            #pragma unroll
            for (int j = 0; j < 4; j++) {
                u64 w = W1u[(t + 32*j)*33 + dp];
                u0p[j] = fma2(mv0, w, u0p[j]);
                u1p[j] = fma2(mv1, w, u1p[j]);
            }
        }
        #pragma unroll
        for (int j = 0; j < 4; j++) {
            U0[t + 32*j] = fmaxf(hsum2(u0p[j]) + cb[192 + t + 32*j], 0.f);
            U1[t + 32*j] = fmaxf(hsum2(u1p[j]) + cb[192 + t + 32*j], 0.f);
        }
        __syncwarp();

        // ---- FFN down (d<128 -> 64 d-pairs) ----
        u64 f0p0 = 0ull, f0p1 = 0ull, f1p0 = 0ull, f1p1 = 0ull;
        #pragma unroll
        for (int dp = 0; dp < 64; dp++) {
            u64 uv0 = *(const u64*)&U0[2*dp];
            u64 uv1 = *(const u64*)&U1[2*dp];
            u64 w0 = W2u[t*65 + dp];
            u64 w1 = W2u[(t+32)*65 + dp];
            f0p0 = fma2(uv0, w0, f0p0);
            f0p1 = fma2(uv0, w1, f0p1);
            f1p0 = fma2(uv1, w0, f1p0);
            f1p1 = fma2(uv1, w1, f1p1);
        }
        float z00 = y00 + hsum2(f0p0) + cb[320+t];
        float z01 = y01 + hsum2(f0p1) + cb[320+t+32];
        float z10 = y10 + hsum2(f1p0) + cb[320+t];
        float z11 = y11 + hsum2(f1p1) + cb[320+t+32];

        // ---- LN2 ----
        s0 = z00+z01; s1 = z10+z11;
        #pragma unroll
        for (int o = 16; o; o >>= 1) {
            s0 += __shfl_xor_sync(0xffffffffu, s0, o);
            s1 += __shfl_xor_sync(0xffffffffu, s1, o);
        }
        mn0 = s0*inv64; mn1 = s1*inv64;
        d00 = z00-mn0; d01 = z01-mn0; d10 = z10-mn1; d11 = z11-mn1;
        v0 = d00*d00 + d01*d01; v1 = d10*d10 + d11*d11;
        #pragma unroll
        for (int o = 16; o; o >>= 1) {
            v0 += __shfl_xor_sync(0xffffffffu, v0, o);
            v1 += __shfl_xor_sync(0xffffffffu, v1, o);
        }
        rs0 = rsqrtf(v0*inv64 + 1e-5f); rs1 = rsqrtf(v1*inv64 + 1e-5f);
        float q00 = d00*rs0*cb[384+t]    + cb[448+t];
        float q01 = d01*rs0*cb[384+t+32] + cb[448+t+32];
        float q10 = d10*rs1*cb[384+t]    + cb[448+t];
        float q11 = d11*rs1*cb[384+t+32] + cb[448+t+32];
        __syncwarp();
        M0[t] = q00; M0[t+32] = q01;
        M1[t] = q10; M1[t+32] = q11;
        g_h2[r0*64+t] = q00; g_h2[r0*64+t+32] = q01;
        g_h2[r1*64+t] = q10; g_h2[r1*64+t+32] = q11;
        __syncwarp();

        // ---- lm head ----
        u64 l0p0 = 0ull, l0p1 = 0ull, l1p0 = 0ull, l1p1 = 0ull;
        #pragma unroll
        for (int dp = 0; dp < 32; dp++) {
            u64 mv0 = *(const u64*)&M0[2*dp];
            u64 mv1 = *(const u64*)&M1[2*dp];
            u64 w0 = Lmu[t*33 + dp];
            u64 w1 = Lmu[(t+32)*33 + dp];
            l0p0 = fma2(mv0, w0, l0p0);
            l0p1 = fma2(mv0, w1, l0p1);
            l1p0 = fma2(mv1, w0, l1p0);
            l1p1 = fma2(mv1, w1, l1p1);
        }
        float l00 = hsum2(l0p0) + cb[512+t];
        float l01 = hsum2(l0p1) + cb[512+t+32];
        float l10 = hsum2(l1p0) + cb[512+t];
        float l11 = hsum2(l1p1) + cb[512+t+32];

        float m0 = fmaxf(l00, l01), m1 = fmaxf(l10, l11);
        #pragma unroll
        for (int o = 16; o; o >>= 1) {
            m0 = fmaxf(m0, __shfl_xor_sync(0xffffffffu, m0, o));
            m1 = fmaxf(m1, __shfl_xor_sync(0xffffffffu, m1, o));
        }
        float es0 = __expf(l00-m0) + __expf(l01-m0);
        float es1 = __expf(l10-m1) + __expf(l11-m1);
        #pragma unroll
        for (int o = 16; o; o >>= 1) {
            es0 += __shfl_xor_sync(0xffffffffu, es0, o);
            es1 += __shfl_xor_sync(0xffffffffu, es1, o);
        }
        float lse0 = m0 + logf(es0);
        float lse1 = m1 + logf(es1);

        int l0pos = r0 & 511, l1pos = r1 & 511;
        int tgt0 = (l0pos == 511) ? 0 : seq[r0+1];
        int tgt1 = (l1pos == 511) ? 0 : seq[r1+1];
        float cand0 = (tgt0 < 32) ? l00 : l01;
        float cand1 = (tgt1 < 32) ? l10 : l11;
        float tl0 = __shfl_sync(0xffffffffu, cand0, tgt0 & 31);
        float tl1 = __shfl_sync(0xffffffffu, cand1, tgt1 & 31);

        float gv0 = q00*cb[576+t] + q01*cb[576+t+32];
        float gv1 = q10*cb[576+t] + q11*cb[576+t+32];
        #pragma unroll
        for (int o = 16; o; o >>= 1) {
            gv0 += __shfl_xor_sync(0xffffffffu, gv0, o);
            gv1 += __shfl_xor_sync(0xffffffffu, gv1, o);
        }
        __syncwarp();

        if (lane == 0) {
            g_gs[r0] = gv0 + cb[640];
            g_gs[r1] = gv1 + cb[640];
            out[1 + r0] = (l0pos == 511) ? 0.f : (lse0 - tl0);
            out[1 + r1] = (l1pos == 511) ? 0.f : (lse1 - tl1);
        }
        __syncwarp();
    }
}

// ============================================================
// K4: one warp per batch; top-8 + reader entirely in registers
// ============================================================
__global__ void __launch_bounds__(256) k4_reader(
        const float* __restrict__ qembed,
        const float* __restrict__ qpW, const float* __restrict__ qpb,
        const float* __restrict__ opW, const float* __restrict__ opb,
        const int* __restrict__ query, const int* __restrict__ target)
{
    __shared__ float sqp[64*65];   // padded: [o*65+d]
    __shared__ float sop[64*65];
    int tid = threadIdx.x;
    for (int i = tid; i < 4096; i += 256) {
        int o = i >> 6, d = i & 63;
        sqp[o*65 + d] = qpW[i];
        sop[o*65 + d] = opW[i];
    }
    __syncthreads();

    int warp = tid >> 5, lane = tid & 31;
    int b = blockIdx.x*8 + warp;

    // gate scores -> registers
    float gsv[16];
    #pragma unroll
    for (int i = 0; i < 16; i++) gsv[i] = g_gs[b*512 + lane + 32*i];

    // stable top-8 (desc value, ties -> lower index)
    int chosen[8];
    #pragma unroll
    for (int k = 0; k < 8; k++) {
        float bv = gsv[0]; int bi = lane;
        #pragma unroll
        for (int i = 1; i < 16; i++) {
            int idx = lane + 32*i;
            if (gsv[i] > bv) { bv = gsv[i]; bi = idx; }
        }
        #pragma unroll
        for (int o = 16; o; o >>= 1) {
            float ov = __shfl_xor_sync(0xffffffffu, bv, o);
            int   oi = __shfl_xor_sync(0xffffffffu, bi, o);
            if (ov > bv || (ov == bv && oi < bi)) { bv = ov; bi = oi; }
        }
        chosen[k] = bi;
        #pragma unroll
        for (int i = 0; i < 16; i++)
            if (bi == lane + 32*i) gsv[i] = -CUDART_INF_F;
    }

    // memory keys: lane holds dims (lane, lane+32) of each of 8 keys
    float kd0[8], kd1[8];
    #pragma unroll
    for (int k = 0; k < 8; k++) {
        const float* hp = &g_h2[(b*512 + chosen[k])*64];
        kd0[k] = hp[lane];
        kd1[k] = hp[lane+32];
    }

    int qt = query[b];
    float qh0 = qembed[qt*64 + lane], qh1 = qembed[qt*64 + lane + 32];

    // qp = qh @ qp_W^T + qp_b   (outputs lane, lane+32)
    float qp0 = qpb[lane], qp1 = qpb[lane+32];
    #pragma unroll 8
    for (int d = 0; d < 64; d++) {
        float hv = __shfl_sync(0xffffffffu, (d < 32) ? qh0 : qh1, d & 31);
        qp0 += sqp[lane*65 + d] * hv;
        qp1 += sqp[(lane+32)*65 + d] * hv;
    }

    // retrieval scores + softmax over K=8
    float rw[8];
    float mx = -CUDART_INF_F;
    #pragma unroll
    for (int k = 0; k < 8; k++) {
        float p = qp0*kd0[k] + qp1*kd1[k];
        #pragma unroll
        for (int o = 16; o; o >>= 1) p += __shfl_xor_sync(0xffffffffu, p, o);
        rw[k] = p * 0.125f;
        mx = fmaxf(mx, rw[k]);
    }
    float ssum = 0.f;
    #pragma unroll
    for (int k = 0; k < 8; k++) { rw[k] = __expf(rw[k] - mx); ssum += rw[k]; }
    float inv = 1.f / ssum;

    float ret0 = 0.f, ret1 = 0.f;
    #pragma unroll
    for (int k = 0; k < 8; k++) { ret0 += rw[k]*kd0[k]; ret1 += rw[k]*kd1[k]; }
    ret0 *= inv; ret1 *= inv;

    // logits = retrieved @ op_W^T + op_b  (outputs lane, lane+32)
    float l0 = opb[lane], l1 = opb[lane+32];
    #pragma unroll 8
    for (int d = 0; d < 64; d++) {
        float rv = __shfl_sync(0xffffffffu, (d < 32) ? ret0 : ret1, d & 31);
        l0 += sop[lane*65 + d] * rv;
        l1 += sop[(lane+32)*65 + d] * rv;
    }

    float mm = fmaxf(l0, l1);
    #pragma unroll
    for (int o = 16; o; o >>= 1) mm = fmaxf(mm, __shfl_xor_sync(0xffffffffu, mm, o));
    float es = __expf(l0 - mm) + __expf(l1 - mm);
    #pragma unroll
    for (int o = 16; o; o >>= 1) es += __shfl_xor_sync(0xffffffffu, es, o);
    float lse = mm + logf(es);

    int tg = target[b];
    float cand = (tg < 32) ? l0 : l1;
    float tl = __shfl_sync(0xffffffffu, cand, tg & 31);
    if (lane == 0) g_loss[b] = lse - tl;
}

// ============================================================
// K5: mean task loss -> out[0]
// ============================================================
__global__ void k5_final(float* __restrict__ out)
{
    __shared__ float red[256];
    int tid = threadIdx.x;
    red[tid] = g_loss[tid];
    __syncthreads();
    for (int s = 128; s; s >>= 1) {
        if (tid < s) red[tid] += red[tid+s];
        __syncthreads();
    }
    if (tid == 0) out[0] = red[0] * (1.f/256.f);
}

// ============================================================
extern "C" void kernel_launch(void* const* d_in, const int* in_sizes, int n_in,
                              void* d_out, int out_size)
{
    const float* embed  = (const float*)d_in[0];
    const float* qembed = (const float*)d_in[1];
    const float* W_in   = (const float*)d_in[2];
    const float* b_in   = (const float*)d_in[3];
    const float* W_out  = (const float*)d_in[4];
    const float* b_out  = (const float*)d_in[5];
    const float* ln1g   = (const float*)d_in[6];
    const float* ln1b   = (const float*)d_in[7];
    const float* W1     = (const float*)d_in[8];
    const float* b1     = (const float*)d_in[9];
    const float* W2     = (const float*)d_in[10];
    const float* b2     = (const float*)d_in[11];
    const float* ln2g   = (const float*)d_in[12];
    const float* ln2b   = (const float*)d_in[13];
    const float* lmW    = (const float*)d_in[14];
    const float* lmb    = (const float*)d_in[15];
    const float* gateW  = (const float*)d_in[16];
    const float* gateb  = (const float*)d_in[17];
    const float* qpW    = (const float*)d_in[18];
    const float* qpb    = (const float*)d_in[19];
    const float* opW    = (const float*)d_in[20];
    const float* opb    = (const float*)d_in[21];
    const int*   seq    = (const int*)d_in[22];
    const int*   query  = (const int*)d_in[23];
    const int*   target = (const int*)d_in[24];
    float* out = (float*)d_out;

    cudaFuncSetAttribute(k1_embed_qkv, cudaFuncAttributeMaxDynamicSharedMemorySize, K1_SMEM);
    cudaFuncSetAttribute(k2_attn,      cudaFuncAttributeMaxDynamicSharedMemorySize, K2_SMEM);
    cudaFuncSetAttribute(k3_fused,     cudaFuncAttributeMaxDynamicSharedMemorySize, K3_SMEM);

    k1_embed_qkv<<<512, 256, K1_SMEM>>>(embed, W_in, b_in, seq);
    k2_attn<<<512, 256, K2_SMEM>>>();
    k3_fused<<<1024, 256, K3_SMEM>>>(W_out, b_out, ln1g, ln1b, W1, b1, W2, b2,
                                     ln2g, ln2b, lmW, lmb, gateW, gateb, seq, out);
    k4_reader<<<32, 256>>>(qembed, qpW, qpb, opW, opb, query, target);
    k5_final<<<1, 256>>>(out);
}